// round 1
// baseline (speedup 1.0000x reference)
#include <cuda_runtime.h>
#include <math.h>

#define T_LEN 128
#define B_DIM 128
#define I_DIM 128
#define H_DIM 512
#define W_WIN 16
#define G4H   2048   // 4*H
#define IH    640    // I+H

// ---------------- scratch (device globals; no allocation allowed) ----------
__device__ float g_h[2][B_DIM * H_DIM];   // double-buffered hidden state
__device__ float g_c[B_DIM * H_DIM];      // cell state (single buffer ok)
__device__ float g_V[W_WIN * B_DIM * H_DIM]; // V cache: [w][b][j]
__device__ float g_attn[B_DIM * H_DIM];
__device__ float g_Q[B_DIM * H_DIM];

// ---------------- init: h=0, c=0, V[w][b][:] = bv ---------------------------
__global__ void init_kernel(const float* __restrict__ bv) {
    int idx = blockIdx.x * blockDim.x + threadIdx.x;
    int stride = gridDim.x * blockDim.x;
    for (int i = idx; i < B_DIM * H_DIM; i += stride) {
        g_h[0][i] = 0.f;
        g_c[i] = 0.f;
    }
    for (int i = idx; i < W_WIN * B_DIM * H_DIM; i += stride) {
        g_V[i] = bv[i % H_DIM];
    }
}

// ---------------- KA: Q = [x_t|h] @ Wq + bq   AND   V[t%W] = c @ Wv + bv ----
// grid = 128 blocks, 128 threads. Blocks 0..63: Q-GEMM (M=128,N=512,K=640)
// Blocks 64..127: V update (M=128,N=512,K=512). Tile 16x64, TK=16.
__global__ __launch_bounds__(128) void ka_kernel(
    int t,
    const float* __restrict__ x,
    const float* __restrict__ Wq, const float* __restrict__ bq,
    const float* __restrict__ Wv, const float* __restrict__ bv)
{
    __shared__ float As[16][16];
    __shared__ float Ws[16][64];

    int blk = blockIdx.x;
    bool isQ = (blk < 64);
    int bid = isQ ? blk : (blk - 64);
    int m0 = (bid / 8) * 16;   // 8 M-tiles
    int n0 = (bid % 8) * 64;   // 8 N-tiles

    const float* hin = g_h[t & 1];
    const float* xt  = x + (size_t)t * B_DIM * I_DIM;
    const float* Wmat = isQ ? Wq : Wv;
    int Ka = isQ ? IH : H_DIM;

    int tid = threadIdx.x;
    int jj  = tid % 32;        // cols jj and jj+32
    int bg  = tid / 32;        // 0..3 -> rows bg*4 .. bg*4+3

    float acc[4][2] = {};

    for (int kk = 0; kk < Ka; kk += 16) {
        // load A tile (16 k x 16 b) : 256 elems, 2 per thread
        #pragma unroll
        for (int l = 0; l < 2; l++) {
            int idx = tid + l * 128;
            int k = idx % 16, b = idx / 16;
            int gk = kk + k;
            float v;
            if (isQ) {
                v = (gk < I_DIM) ? xt[(m0 + b) * I_DIM + gk]
                                 : hin[(m0 + b) * H_DIM + (gk - I_DIM)];
            } else {
                v = g_c[(m0 + b) * H_DIM + gk];
            }
            As[k][b] = v;
        }
        // load W tile (16 k x 64 n) : 1024 elems, 8 per thread
        #pragma unroll
        for (int l = 0; l < 8; l++) {
            int idx = tid + l * 128;
            int k = idx / 64, j = idx % 64;
            Ws[k][j] = Wmat[(size_t)(kk + k) * H_DIM + n0 + j];
        }
        __syncthreads();
        #pragma unroll
        for (int k = 0; k < 16; k++) {
            float w0 = Ws[k][jj];
            float w1 = Ws[k][jj + 32];
            #pragma unroll
            for (int r = 0; r < 4; r++) {
                float a = As[k][bg * 4 + r];
                acc[r][0] += a * w0;
                acc[r][1] += a * w1;
            }
        }
        __syncthreads();
    }

    const float* bias = isQ ? bq : bv;
    float b0 = bias[n0 + jj];
    float b1 = bias[n0 + jj + 32];
    float* outp = isQ ? g_Q : (g_V + (size_t)(t % W_WIN) * B_DIM * H_DIM);
    #pragma unroll
    for (int r = 0; r < 4; r++) {
        int row = m0 + bg * 4 + r;
        outp[(size_t)row * H_DIM + n0 + jj]      = acc[r][0] + b0;
        outp[(size_t)row * H_DIM + n0 + jj + 32] = acc[r][1] + b1;
    }
}

// ---------------- KB: scores -> softmax -> attn -----------------------------
// grid = 128 blocks (one per batch), 128 threads
__global__ __launch_bounds__(128) void kb_kernel(int t) {
    const float inv_sqrt_dk = 0.044194173824159216f; // 1/sqrt(512)
    int b = blockIdx.x;
    int tid = threadIdx.x;
    __shared__ float sQ[H_DIM];
    __shared__ float sS[W_WIN];
    __shared__ float sP[W_WIN];

    for (int j = tid; j < H_DIM; j += 128) sQ[j] = g_Q[(size_t)b * H_DIM + j];
    __syncthreads();

    int nv = (t + 1 < W_WIN) ? (t + 1) : W_WIN;
    int warp = tid / 32, lane = tid % 32;
    for (int w = warp; w < nv; w += 4) {
        const float* Vp = g_V + (size_t)(w * B_DIM + b) * H_DIM;
        float p = 0.f;
        for (int j = lane; j < H_DIM; j += 32) p += sQ[j] * Vp[j];
        #pragma unroll
        for (int o = 16; o > 0; o >>= 1) p += __shfl_xor_sync(0xffffffffu, p, o);
        if (lane == 0) sS[w] = p * inv_sqrt_dk;
    }
    __syncthreads();
    if (tid == 0) {
        float m = sS[0];
        for (int w = 1; w < nv; w++) m = fmaxf(m, sS[w]);
        float sum = 0.f;
        for (int w = 0; w < nv; w++) { float e = expf(sS[w] - m); sP[w] = e; sum += e; }
        float inv = 1.f / sum;
        for (int w = 0; w < nv; w++) sP[w] *= inv;
    }
    __syncthreads();
    for (int j = tid; j < H_DIM; j += 128) {
        float a = 0.f;
        for (int w = 0; w < nv; w++)
            a += sP[w] * g_V[(size_t)(w * B_DIM + b) * H_DIM + j];
        g_attn[(size_t)b * H_DIM + j] = a;
    }
}

// ---------------- KC: fused cell GEMM + LSTM pointwise ----------------------
// preact[b][g*H+j] = x_t@Wi + h@Wh + attn@Wa + bi + ba ; gates ; c,h update
// grid = 128 blocks (8 M-tiles x 16 N-tiles of j), 128 threads.
// Each (b,j) carries 4 gate accumulators. Tile M=16, Nj=32, TK=16.
__global__ __launch_bounds__(128) void kc_kernel(
    int t,
    const float* __restrict__ x,
    const float* __restrict__ Wi, const float* __restrict__ Wh,
    const float* __restrict__ Wa,
    const float* __restrict__ bi, const float* __restrict__ ba,
    float* __restrict__ out)
{
    __shared__ float As[16][16];
    __shared__ float Ws[16][128]; // [k][g*32 + j]

    int m0 = (blockIdx.x / 16) * 16;
    int n0 = (blockIdx.x % 16) * 32;

    const float* hin  = g_h[t & 1];
    float*       hout = g_h[(t + 1) & 1];
    const float* xt   = x + (size_t)t * B_DIM * I_DIM;

    int tid = threadIdx.x;
    int jj  = tid % 32;
    int bg  = tid / 32;  // 0..3 -> rows bg*4 .. bg*4+3

    float acc[4][4] = {}; // [row][gate]

    for (int seg = 0; seg < 3; seg++) {
        const float* Aseg; const float* Wseg; int Ka; int ldA;
        if (seg == 0)      { Aseg = xt;     Wseg = Wi; Ka = I_DIM; ldA = I_DIM; }
        else if (seg == 1) { Aseg = hin;    Wseg = Wh; Ka = H_DIM; ldA = H_DIM; }
        else               { Aseg = g_attn; Wseg = Wa; Ka = H_DIM; ldA = H_DIM; }

        for (int kk = 0; kk < Ka; kk += 16) {
            #pragma unroll
            for (int l = 0; l < 2; l++) {
                int idx = tid + l * 128;
                int k = idx % 16, b = idx / 16;
                As[k][b] = Aseg[(size_t)(m0 + b) * ldA + kk + k];
            }
            #pragma unroll
            for (int l = 0; l < 16; l++) {
                int idx = tid + l * 128;
                int k = idx / 128, c = idx % 128;
                int g = c / 32, j = c % 32;
                Ws[k][c] = Wseg[(size_t)(kk + k) * G4H + g * H_DIM + n0 + j];
            }
            __syncthreads();
            #pragma unroll
            for (int k = 0; k < 16; k++) {
                float a0 = As[k][bg * 4 + 0];
                float a1 = As[k][bg * 4 + 1];
                float a2 = As[k][bg * 4 + 2];
                float a3 = As[k][bg * 4 + 3];
                #pragma unroll
                for (int g = 0; g < 4; g++) {
                    float w = Ws[k][g * 32 + jj];
                    acc[0][g] += a0 * w;
                    acc[1][g] += a1 * w;
                    acc[2][g] += a2 * w;
                    acc[3][g] += a3 * w;
                }
            }
            __syncthreads();
        }
    }

    int j = n0 + jj;
    float bias_i = bi[j]             + ba[j];
    float bias_f = bi[H_DIM + j]     + ba[H_DIM + j];
    float bias_o = bi[2 * H_DIM + j] + ba[2 * H_DIM + j];
    float bias_g = bi[3 * H_DIM + j] + ba[3 * H_DIM + j];

    #pragma unroll
    for (int r = 0; r < 4; r++) {
        int b = m0 + bg * 4 + r;
        float pi = acc[r][0] + bias_i;
        float pf = acc[r][1] + bias_f;
        float po = acc[r][2] + bias_o;
        float pg = acc[r][3] + bias_g;
        float ig = 1.f / (1.f + expf(-pi));
        float fg = 1.f / (1.f + expf(-pf));
        float og = 1.f / (1.f + expf(-po));
        float gg = tanhf(pg);
        size_t idx = (size_t)b * H_DIM + j;
        float cn = g_c[idx] * fg + ig * gg;
        float hn = og * tanhf(cn);
        g_c[idx] = cn;
        hout[idx] = hn;
        out[(size_t)t * B_DIM * H_DIM + idx] = hn;
    }
}

// ---------------- launcher --------------------------------------------------
extern "C" void kernel_launch(void* const* d_in, const int* in_sizes, int n_in,
                              void* d_out, int out_size) {
    const float* x  = (const float*)d_in[0];
    const float* Wi = (const float*)d_in[1];
    const float* bi = (const float*)d_in[2];
    const float* Wh = (const float*)d_in[3];
    const float* Wv = (const float*)d_in[4];
    const float* bv = (const float*)d_in[5];
    const float* Wq = (const float*)d_in[6];
    const float* bq = (const float*)d_in[7];
    const float* Wa = (const float*)d_in[8];
    const float* ba = (const float*)d_in[9];
    float* out = (float*)d_out;

    init_kernel<<<1024, 256>>>(bv);
    for (int t = 0; t < T_LEN; t++) {
        ka_kernel<<<128, 128>>>(t, x, Wq, bq, Wv, bv);
        kb_kernel<<<128, 128>>>(t);
        kc_kernel<<<128, 128>>>(t, x, Wi, Wh, Wa, bi, ba, out);
    }
}

// round 2
// speedup vs baseline: 1.5651x; 1.5651x over previous
#include <cuda_runtime.h>
#include <math.h>

#define T_LEN 128
#define B_DIM 128
#define I_DIM 128
#define H_DIM 512
#define W_WIN 16
#define G4H   2048   // 4*H
#define IH    640    // I+H

// ---------------- scratch (device globals; no allocation allowed) ----------
__device__ float g_h[2][B_DIM * H_DIM];   // double-buffered hidden state
__device__ float g_c[B_DIM * H_DIM];      // cell state
__device__ float g_V[W_WIN * B_DIM * H_DIM]; // V cache: [w][b][j]
__device__ float g_attn[B_DIM * H_DIM];
__device__ float g_Q[B_DIM * H_DIM];

// ---------------- cp.async helpers -----------------------------------------
__device__ __forceinline__ unsigned smem_u32(const void* p) {
    return (unsigned)__cvta_generic_to_shared(p);
}
__device__ __forceinline__ void cp16(void* dst, const void* src) {
    asm volatile("cp.async.cg.shared.global [%0], [%1], 16;\n"
                 :: "r"(smem_u32(dst)), "l"(src));
}
__device__ __forceinline__ void cp_commit() {
    asm volatile("cp.async.commit_group;\n" ::: "memory");
}
__device__ __forceinline__ void cp_wait1() {
    asm volatile("cp.async.wait_group 1;\n" ::: "memory");
}
__device__ __forceinline__ void cp_wait0() {
    asm volatile("cp.async.wait_group 0;\n" ::: "memory");
}

// ---------------- init: h=0, c=0, V[w][b][:] = bv ---------------------------
__global__ void init_kernel(const float* __restrict__ bv) {
    int idx = blockIdx.x * blockDim.x + threadIdx.x;
    int stride = gridDim.x * blockDim.x;
    for (int i = idx; i < B_DIM * H_DIM; i += stride) {
        g_h[0][i] = 0.f;
        g_c[i] = 0.f;
    }
    for (int i = idx; i < W_WIN * B_DIM * H_DIM; i += stride) {
        g_V[i] = bv[i % H_DIM];
    }
}

// ---------------- KA: Q = [x_t|h] @ Wq + bq   AND   V[t%W] = c @ Wv + bv ----
// grid = 64 blocks x 256 threads.
// Blocks 0..31 : Q-GEMM (M=128, N=512, K=640), tiles 32x64, TK=32
// Blocks 32..63: V-GEMM (M=128, N=512, K=512)
__global__ __launch_bounds__(256) void ka_kernel(
    int t,
    const float* __restrict__ x,
    const float* __restrict__ Wq, const float* __restrict__ bq,
    const float* __restrict__ Wv, const float* __restrict__ bv)
{
    __shared__ float As[2][32][36];   // [stage][row][k] (pad 36 for banks+align)
    __shared__ float Ws[2][32][64];   // [stage][k][n]

    const int blk = blockIdx.x;
    const bool isQ = (blk < 32);
    const int bid = blk & 31;
    const int m0 = (bid >> 3) * 32;     // 4 M-tiles
    const int n0 = (bid & 7) * 64;      // 8 N-tiles

    const float* __restrict__ hin = g_h[t & 1];
    const float* __restrict__ xt  = x + (size_t)t * B_DIM * I_DIM;
    const float* __restrict__ Wmat = isQ ? Wq : Wv;
    const int nt = isQ ? (IH / 32) : (H_DIM / 32);   // 20 or 16 k-tiles

    const int tid = threadIdx.x;
    const int tc  = tid & 15;          // col group: cols tc*4 .. tc*4+3
    const int tr  = tid >> 4;          // 0..15 -> rows tr*2, tr*2+1

    // A-chunk assignment: 256 chunks (32 rows x 8 chunks), 1 per thread
    const int a_row = tid >> 3;
    const int a_c4  = (tid & 7) * 4;
    // W-chunk assignment: 512 chunks (32 k x 16 chunks), 2 per thread

    float acc[2][4] = {};

    // issue stage for k-tile `it`
    auto issue = [&](int it, int s) {
        const int kk = it * 32;
        // A tile: rows m0..m0+31, k kk..kk+31
        {
            int gk = kk + a_c4;
            const float* src;
            if (isQ) {
                src = (gk < I_DIM) ? (xt + (size_t)(m0 + a_row) * I_DIM + gk)
                                   : (hin + (size_t)(m0 + a_row) * H_DIM + (gk - I_DIM));
            } else {
                src = g_c + (size_t)(m0 + a_row) * H_DIM + kk + a_c4;
            }
            cp16(&As[s][a_row][a_c4], src);
        }
        // W tile
        #pragma unroll
        for (int l = 0; l < 2; l++) {
            int id = tid + l * 256;
            int k = id >> 4, c4 = (id & 15) * 4;
            cp16(&Ws[s][k][c4], Wmat + (size_t)(kk + k) * H_DIM + n0 + c4);
        }
        cp_commit();
    };

    issue(0, 0);
    for (int it = 0; it < nt; it++) {
        const int s = it & 1;
        if (it + 1 < nt) { issue(it + 1, s ^ 1); cp_wait1(); }
        else             { cp_wait0(); }
        __syncthreads();

        #pragma unroll
        for (int k4 = 0; k4 < 32; k4 += 4) {
            float a0v[4], a1v[4];
            *(float4*)a0v = *(const float4*)&As[s][tr * 2][k4];
            *(float4*)a1v = *(const float4*)&As[s][tr * 2 + 1][k4];
            #pragma unroll
            for (int q = 0; q < 4; q++) {
                float wv[4];
                *(float4*)wv = *(const float4*)&Ws[s][k4 + q][tc * 4];
                #pragma unroll
                for (int c = 0; c < 4; c++) {
                    acc[0][c] += a0v[q] * wv[c];
                    acc[1][c] += a1v[q] * wv[c];
                }
            }
        }
        __syncthreads();
    }

    const float* bias = isQ ? bq : bv;
    float* outp = isQ ? g_Q : (g_V + (size_t)(t % W_WIN) * B_DIM * H_DIM);
    #pragma unroll
    for (int r = 0; r < 2; r++) {
        int row = m0 + tr * 2 + r;
        float4 o;
        o.x = acc[r][0] + bias[n0 + tc * 4 + 0];
        o.y = acc[r][1] + bias[n0 + tc * 4 + 1];
        o.z = acc[r][2] + bias[n0 + tc * 4 + 2];
        o.w = acc[r][3] + bias[n0 + tc * 4 + 3];
        *(float4*)(outp + (size_t)row * H_DIM + n0 + tc * 4) = o;
    }
}

// ---------------- KB: scores -> softmax -> attn -----------------------------
// grid = 128 blocks (one per batch), 128 threads
__global__ __launch_bounds__(128) void kb_kernel(int t) {
    const float inv_sqrt_dk = 0.044194173824159216f; // 1/sqrt(512)
    int b = blockIdx.x;
    int tid = threadIdx.x;
    __shared__ float sQ[H_DIM];
    __shared__ float sS[W_WIN];
    __shared__ float sP[W_WIN];

    for (int j = tid; j < H_DIM; j += 128) sQ[j] = g_Q[(size_t)b * H_DIM + j];
    __syncthreads();

    int nv = (t + 1 < W_WIN) ? (t + 1) : W_WIN;
    int warp = tid / 32, lane = tid % 32;
    for (int w = warp; w < nv; w += 4) {
        const float* Vp = g_V + (size_t)(w * B_DIM + b) * H_DIM;
        float p = 0.f;
        for (int j = lane; j < H_DIM; j += 32) p += sQ[j] * Vp[j];
        #pragma unroll
        for (int o = 16; o > 0; o >>= 1) p += __shfl_xor_sync(0xffffffffu, p, o);
        if (lane == 0) sS[w] = p * inv_sqrt_dk;
    }
    __syncthreads();
    if (tid == 0) {
        float m = sS[0];
        for (int w = 1; w < nv; w++) m = fmaxf(m, sS[w]);
        float sum = 0.f;
        for (int w = 0; w < nv; w++) { float e = expf(sS[w] - m); sP[w] = e; sum += e; }
        float inv = 1.f / sum;
        for (int w = 0; w < nv; w++) sP[w] *= inv;
    }
    __syncthreads();
    for (int j = tid; j < H_DIM; j += 128) {
        float a = 0.f;
        for (int w = 0; w < nv; w++)
            a += sP[w] * g_V[(size_t)(w * B_DIM + b) * H_DIM + j];
        g_attn[(size_t)b * H_DIM + j] = a;
    }
}

// ---------------- KC: fused cell GEMM + LSTM pointwise ----------------------
// preact = x_t@Wi + h@Wh + attn@Wa + bi + ba (virtual K=1152), gate-aware tiles
// grid = 128 blocks (4 M-tiles x 32 j-tiles), 256 threads.
// Tile: BM=32 rows x 16 j-cols x 4 gates, TK=32. Thread: 2 rows x 4 gates.
__global__ __launch_bounds__(256) void kc_kernel(
    int t,
    const float* __restrict__ x,
    const float* __restrict__ Wi, const float* __restrict__ Wh,
    const float* __restrict__ Wa,
    const float* __restrict__ bi, const float* __restrict__ ba,
    float* __restrict__ out)
{
    __shared__ float As[2][32][36];   // [stage][row][k]
    __shared__ float Ws[2][32][64];   // [stage][k][g*16 + j]

    const int m0 = (blockIdx.x >> 5) * 32;  // 4 M-tiles
    const int j0 = (blockIdx.x & 31) * 16;  // 32 j-tiles

    const float* __restrict__ hin  = g_h[t & 1];
    float*       __restrict__ hout = g_h[(t + 1) & 1];
    const float* __restrict__ xt   = x + (size_t)t * B_DIM * I_DIM;

    const int tid = threadIdx.x;
    const int tj  = tid & 15;          // j within tile
    const int tr  = tid >> 4;          // 0..15 -> rows tr*2, tr*2+1

    const int a_row = tid >> 3;
    const int a_c4  = (tid & 7) * 4;

    float acc[2][4] = {};              // [row][gate]

    // virtual K = 1152 : [0,128)=x/Wi  [128,640)=h/Wh  [640,1152)=attn/Wa
    auto issue = [&](int it, int s) {
        const int kk = it * 32;
        const float* Aseg; const float* Wseg; int ldA; int koff;
        if (kk < I_DIM)       { Aseg = xt;     Wseg = Wi; ldA = I_DIM; koff = kk; }
        else if (kk < IH)     { Aseg = hin;    Wseg = Wh; ldA = H_DIM; koff = kk - I_DIM; }
        else                  { Aseg = g_attn; Wseg = Wa; ldA = H_DIM; koff = kk - IH; }
        // A tile
        cp16(&As[s][a_row][a_c4],
             Aseg + (size_t)(m0 + a_row) * ldA + koff + a_c4);
        // W tile: per k-row, 4 gates x 16 j = 16 chunks; 32 rows -> 512 chunks
        #pragma unroll
        for (int l = 0; l < 2; l++) {
            int id = tid + l * 256;
            int k = id >> 4;
            int rem = id & 15;
            int g = rem >> 2;
            int jc = (rem & 3) * 4;
            cp16(&Ws[s][k][g * 16 + jc],
                 Wseg + (size_t)(koff + k) * G4H + g * H_DIM + j0 + jc);
        }
        cp_commit();
    };

    const int nt = 36;  // 1152/32
    issue(0, 0);
    for (int it = 0; it < nt; it++) {
        const int s = it & 1;
        if (it + 1 < nt) { issue(it + 1, s ^ 1); cp_wait1(); }
        else             { cp_wait0(); }
        __syncthreads();

        #pragma unroll
        for (int k4 = 0; k4 < 32; k4 += 4) {
            float a0v[4], a1v[4];
            *(float4*)a0v = *(const float4*)&As[s][tr * 2][k4];
            *(float4*)a1v = *(const float4*)&As[s][tr * 2 + 1][k4];
            #pragma unroll
            for (int q = 0; q < 4; q++) {
                #pragma unroll
                for (int g = 0; g < 4; g++) {
                    float w = Ws[s][k4 + q][g * 16 + tj];
                    acc[0][g] += a0v[q] * w;
                    acc[1][g] += a1v[q] * w;
                }
            }
        }
        __syncthreads();
    }

    const int j = j0 + tj;
    const float bias_i = bi[j]             + ba[j];
    const float bias_f = bi[H_DIM + j]     + ba[H_DIM + j];
    const float bias_o = bi[2 * H_DIM + j] + ba[2 * H_DIM + j];
    const float bias_g = bi[3 * H_DIM + j] + ba[3 * H_DIM + j];

    #pragma unroll
    for (int r = 0; r < 2; r++) {
        int b = m0 + tr * 2 + r;
        float pi = acc[r][0] + bias_i;
        float pf = acc[r][1] + bias_f;
        float po = acc[r][2] + bias_o;
        float pg = acc[r][3] + bias_g;
        float ig = 1.f / (1.f + expf(-pi));
        float fg = 1.f / (1.f + expf(-pf));
        float og = 1.f / (1.f + expf(-po));
        float gg = tanhf(pg);
        size_t idx = (size_t)b * H_DIM + j;
        float cn = g_c[idx] * fg + ig * gg;
        float hn = og * tanhf(cn);
        g_c[idx] = cn;
        hout[idx] = hn;
        out[(size_t)t * B_DIM * H_DIM + idx] = hn;
    }
}

// ---------------- launcher --------------------------------------------------
extern "C" void kernel_launch(void* const* d_in, const int* in_sizes, int n_in,
                              void* d_out, int out_size) {
    const float* x  = (const float*)d_in[0];
    const float* Wi = (const float*)d_in[1];
    const float* bi = (const float*)d_in[2];
    const float* Wh = (const float*)d_in[3];
    const float* Wv = (const float*)d_in[4];
    const float* bv = (const float*)d_in[5];
    const float* Wq = (const float*)d_in[6];
    const float* bq = (const float*)d_in[7];
    const float* Wa = (const float*)d_in[8];
    const float* ba = (const float*)d_in[9];
    float* out = (float*)d_out;

    init_kernel<<<1024, 256>>>(bv);
    for (int t = 0; t < T_LEN; t++) {
        ka_kernel<<<64, 256>>>(t, x, Wq, bq, Wv, bv);
        kb_kernel<<<128, 128>>>(t);
        kc_kernel<<<128, 256>>>(t, x, Wi, Wh, Wa, bi, ba, out);
    }
}